// round 7
// baseline (speedup 1.0000x reference)
#include <cuda_runtime.h>
#include <cstdint>

#define BB 256
#define LL 1024
#define TT 128
#define GRID 152

#define FMA2(d, a, b, c) \
    asm("fma.rn.f32x2 %0, %1, %2, %3;" : "=l"(d) : "l"(a), "l"(b), "l"(c))
#define ADD2(d, a, b) \
    asm("add.rn.f32x2 %0, %1, %2;" : "=l"(d) : "l"(a), "l"(b))

// ---------------------------------------------------------------------------
// One fused kernel. Per CTA:
//   - sniff index dtype (int32 vs int64) from sequence_lengths layout
//   - build LPT schedule locally (rank by counting; no globals, no atomics)
//   - per batch: sequence score (gather) + forward recursion
// Recursion state is the raw stabilized dot 'ea' — NO log/exp on the critical
// path: ea(l+1) = acc(l) * exp(inp(l) - d(l-1)), offset increments d tracked
// via exponent bits (lagged broadcast). Dot uses packed fma.rn.f32x2.
// ---------------------------------------------------------------------------
__global__ void __launch_bounds__(128)
crf_all(const float* __restrict__ inputs,
        const int*   __restrict__ tags32,
        const int*   __restrict__ slen32,
        const float* __restrict__ trans,
        float* __restrict__ out)
{
    const int t = threadIdx.x;

    // int64 layout => odd words of seqlen are high words (0); int32 => >=1.
    const int stride = ((slen32[1] | slen32[3] | slen32[5] | slen32[7]) == 0) ? 2 : 1;

    __shared__ int slen[BB];
    __shared__ int inv[BB];                       // inv[rank] = batch id
    __shared__ __align__(16) float sh_ea[2][TT];  // stabilized alphas, dbl buf
    __shared__ float sh_d[2];                     // offset increment broadcast
    __shared__ float sh_red[TT];                  // reduction scratch

    for (int i = t; i < BB; i += 128) {
        int v = slen32[(size_t)i * stride];
        if (v < 1) v = 1; if (v > LL) v = LL;
        slen[i] = v;
    }
    __syncthreads();

    // local LPT schedule: rank batches by descending length (unique keys)
    for (int i = t; i < BB; i += 128) {
        unsigned key_i = ((unsigned)(slen[i]) << 8) | (unsigned)i;
        int r = 0;
        for (int j = 0; j < BB; j++) {
            unsigned key_j = ((unsigned)(slen[j]) << 8) | (unsigned)j;
            r += (key_j > key_i) ? 1 : 0;
        }
        inv[r] = i;
    }

    // exp(trans) column for this thread's tag, packed f32x2 (64 x 64-bit regs)
    unsigned long long eT2[TT / 2];
    #pragma unroll
    for (int k = 0; k < TT / 2; k++) {
        float e0 = __expf(trans[(2 * k + 0) * TT + t]);
        float e1 = __expf(trans[(2 * k + 1) * TT + t]);
        asm("mov.b64 %0, {%1, %2};" : "=l"(eT2[k]) : "f"(e0), "f"(e1));
    }
    __syncthreads();                              // inv[] ready

    // static schedule: CTA i -> rank i; CTAs 0..(BB-1-GRID) also -> rank 255-i
    const int nb = ((int)blockIdx.x <= BB - 1 - GRID) ? 2 : 1;

    for (int q = 0; q < nb; q++) {
        int rank = (q == 0) ? (int)blockIdx.x : (BB - 1 - (int)blockIdx.x);
        int b = inv[rank];
        int len = slen[b];
        int nsteps = len - 1; if (nsteps < 1) nsteps = 1;
        const float* inp = inputs + (size_t)b * LL * TT;
        const int*   tg  = tags32 + (size_t)b * LL * stride;

        // ---- sequence score: unary + transition gathers, masked ----
        float s = 0.f;
        for (int l = t; l < len; l += 128) {
            int cur = tg[(size_t)l * stride] & (TT - 1);
            s += inp[(size_t)l * TT + cur];
            if (l > 0) {
                int prev = tg[(size_t)(l - 1) * stride] & (TT - 1);
                s += trans[prev * TT + cur];
            }
        }
        sh_red[t] = s;
        __syncthreads();
        for (int o = 64; o > 0; o >>= 1) {
            if (t < o) sh_red[t] += sh_red[t + o];
            __syncthreads();
        }
        float seqscore = sh_red[0];
        __syncthreads();                          // WAR guard on sh_red

        // ---- forward recursion (log-free critical path) ----
        float M0 = inp[0];                        // broadcast offset M(0)
        float Msum = M0;                          // absolute offset accumulator
        float ea = __expf(inp[t] - M0);           // exp(alpha(0) - M(0))
        float d_local = 0.f;                      // d(0) (thread 0's copy used)
        float inp_cur = inp[TT + t];              // row 1 (always exists)
        int buf = 0;

        for (int l = 1; l <= nsteps; l++) {
            sh_ea[buf][t] = ea;
            if (t == 0) sh_d[buf] = d_local;      // d(l-1)
            __syncthreads();
            float d_prev = sh_d[buf];
            float e_t = __expf(inp_cur - d_prev); // MUFU hides under FMA issue
            int nrow = (l + 1 < LL) ? l + 1 : LL - 1;
            float inp_next = inp[(size_t)nrow * TT + t];

            const ulonglong2* ev =
                reinterpret_cast<const ulonglong2*>(sh_ea[buf]);
            unsigned long long a0 = 0, a1 = 0, a2 = 0, a3 = 0;
            #pragma unroll
            for (int k = 0; k < TT / 8; k++) {    // 32 LDS.128 + 64 FFMA2
                ulonglong2 e = ev[2 * k + 0];
                FMA2(a0, e.x, eT2[4 * k + 0], a0);
                FMA2(a1, e.y, eT2[4 * k + 1], a1);
                ulonglong2 f = ev[2 * k + 1];
                FMA2(a2, f.x, eT2[4 * k + 2], a2);
                FMA2(a3, f.y, eT2[4 * k + 3], a3);
            }
            unsigned long long s01, s23, sall;
            ADD2(s01, a0, a1);
            ADD2(s23, a2, a3);
            ADD2(sall, s01, s23);
            float lo, hi;
            asm("mov.b64 {%0, %1}, %2;" : "=f"(lo), "=f"(hi) : "l"(sall));
            float acc = lo + hi;

            ea = acc * e_t;                       // exp(alpha(l) - M(l))
            if (t == 0)                           // d(l) from exponent bits
                d_local = inp_cur + 0.6931471805599453f *
                          (float)((int)(__float_as_uint(acc) >> 23) - 127);
            Msum += d_prev;                       // M(l) running total
            inp_cur = inp_next;
            buf ^= 1;
        }

        // ---- log_norm = M(ns) + ln(sum_t ea_t); ea bounded by construction ----
        sh_red[t] = ea;
        __syncthreads();
        for (int o = 64; o > 0; o >>= 1) {
            if (t < o) sh_red[t] += sh_red[t + o];
            __syncthreads();
        }
        if (t == 0) out[b] = seqscore - (Msum + __logf(sh_red[0]));
        __syncthreads();                          // protect shared before next batch
    }
}

// ---------------------------------------------------------------------------
extern "C" void kernel_launch(void* const* d_in, const int* in_sizes, int n_in,
                              void* d_out, int out_size) {
    const float* inputs = (const float*)d_in[0];
    const int*   tags32 = (const int*)d_in[1];
    const int*   slen32 = (const int*)d_in[2];
    const float* trans  = (const float*)d_in[3];
    float* outp = (float*)d_out;

    crf_all<<<GRID, 128>>>(inputs, tags32, slen32, trans, outp);
}

// round 8
// speedup vs baseline: 1.1760x; 1.1760x over previous
#include <cuda_runtime.h>
#include <cuda_bf16.h>
#include <cstdint>

#define BB 256
#define LL 1024
#define TT 128
#define GRID 152

// ---------------------------------------------------------------------------
// One fused kernel. Per CTA:
//   - sniff index dtype (int32 vs int64) from sequence_lengths layout
//   - build LPT schedule locally (rank by counting; no globals, no atomics)
//   - per batch: sequence score (gather) + forward recursion
// Recursion state: raw stabilized dot 'acc' — no log/exp on the critical
// path (verified round 7). Dot product in bf16 HFMA2 (2 MACs/instr, rt=2):
// 64 HFMA2/thread vs 128 FFMA -> half the per-SMSP issue floor.
// ---------------------------------------------------------------------------
__global__ void __launch_bounds__(128)
crf_all(const float* __restrict__ inputs,
        const int*   __restrict__ tags32,
        const int*   __restrict__ slen32,
        const float* __restrict__ trans,
        float* __restrict__ out)
{
    const int t = threadIdx.x;

    // int64 layout => odd words of seqlen are high words (0); int32 => >=1.
    const int stride = ((slen32[1] | slen32[3] | slen32[5] | slen32[7]) == 0) ? 2 : 1;

    __shared__ int slen[BB];
    __shared__ int inv[BB];                            // inv[rank] = batch id
    __shared__ __align__(16) __nv_bfloat16 sh_ea[2][TT];  // stabilized alphas
    __shared__ float sh_d[2];                          // offset increment bcast
    __shared__ float sh_red[TT];                       // reduction scratch

    for (int i = t; i < BB; i += 128) {
        int v = slen32[(size_t)i * stride];
        if (v < 1) v = 1; if (v > LL) v = LL;
        slen[i] = v;
    }
    __syncthreads();

    // local LPT schedule: rank batches by descending length (unique keys)
    for (int i = t; i < BB; i += 128) {
        unsigned key_i = ((unsigned)(slen[i]) << 8) | (unsigned)i;
        int r = 0;
        for (int j = 0; j < BB; j++) {
            unsigned key_j = ((unsigned)(slen[j]) << 8) | (unsigned)j;
            r += (key_j > key_i) ? 1 : 0;
        }
        inv[r] = i;
    }

    // exp(trans) column for this thread's tag, packed bf16x2 (64 regs)
    __nv_bfloat162 eT2[TT / 2];
    #pragma unroll
    for (int k = 0; k < TT / 2; k++) {
        float e0 = __expf(trans[(2 * k + 0) * TT + t]);
        float e1 = __expf(trans[(2 * k + 1) * TT + t]);
        eT2[k] = __floats2bfloat162_rn(e0, e1);
    }
    __syncthreads();                                   // inv[] ready

    // static schedule: CTA i -> rank i; CTAs 0..(BB-1-GRID) also -> rank 255-i
    const int nb = ((int)blockIdx.x <= BB - 1 - GRID) ? 2 : 1;

    for (int q = 0; q < nb; q++) {
        int rank = (q == 0) ? (int)blockIdx.x : (BB - 1 - (int)blockIdx.x);
        int b = inv[rank];
        int len = slen[b];
        int nsteps = len - 1; if (nsteps < 1) nsteps = 1;
        const float* inp = inputs + (size_t)b * LL * TT;
        const int*   tg  = tags32 + (size_t)b * LL * stride;

        // ---- sequence score: unary + transition gathers, masked ----
        float s = 0.f;
        for (int l = t; l < len; l += 128) {
            int cur = tg[(size_t)l * stride] & (TT - 1);
            s += inp[(size_t)l * TT + cur];
            if (l > 0) {
                int prev = tg[(size_t)(l - 1) * stride] & (TT - 1);
                s += trans[prev * TT + cur];
            }
        }
        sh_red[t] = s;
        __syncthreads();
        for (int o = 64; o > 0; o >>= 1) {
            if (t < o) sh_red[t] += sh_red[t + o];
            __syncthreads();
        }
        float seqscore = sh_red[0];
        __syncthreads();                               // WAR guard on sh_red

        // ---- forward recursion (log-free critical path, bf16 dot) ----
        float M0 = inp[0];                             // broadcast offset M(0)
        float Msum = M0;                               // absolute offset accum
        float ea_f = __expf(inp[t] - M0);              // exp(alpha(0) - M(0))
        float d_local = 0.f;                           // d(0) (thread 0's)
        float inp_cur = inp[TT + t];                   // row 1 (always exists)
        int buf = 0;

        for (int l = 1; l <= nsteps; l++) {
            sh_ea[buf][t] = __float2bfloat16(ea_f);
            if (t == 0) sh_d[buf] = d_local;           // d(l-1)
            __syncthreads();
            float d_prev = sh_d[buf];
            float e_t = __expf(inp_cur - d_prev);      // MUFU hides under issue
            int nrow = (l + 1 < LL) ? l + 1 : LL - 1;
            float inp_next = inp[(size_t)nrow * TT + t];

            const uint4* ev = reinterpret_cast<const uint4*>(sh_ea[buf]);
            __nv_bfloat162 zz = __floats2bfloat162_rn(0.f, 0.f);
            __nv_bfloat162 a0 = zz, a1 = zz, a2 = zz, a3 = zz;
            #pragma unroll
            for (int k = 0; k < TT / 8; k++) {         // 16 LDS.128 + 64 HFMA2
                uint4 e = ev[k];
                a0 = __hfma2(*reinterpret_cast<__nv_bfloat162*>(&e.x),
                             eT2[4 * k + 0], a0);
                a1 = __hfma2(*reinterpret_cast<__nv_bfloat162*>(&e.y),
                             eT2[4 * k + 1], a1);
                a2 = __hfma2(*reinterpret_cast<__nv_bfloat162*>(&e.z),
                             eT2[4 * k + 2], a2);
                a3 = __hfma2(*reinterpret_cast<__nv_bfloat162*>(&e.w),
                             eT2[4 * k + 3], a3);
            }
            // fp32 combine of the 8 bf16 partial lanes
            float2 f0 = __bfloat1622float2(a0);
            float2 f1 = __bfloat1622float2(a1);
            float2 f2 = __bfloat1622float2(a2);
            float2 f3 = __bfloat1622float2(a3);
            float acc = ((f0.x + f0.y) + (f1.x + f1.y))
                      + ((f2.x + f2.y) + (f3.x + f3.y));

            ea_f = acc * e_t;                          // exp(alpha(l) - M(l))
            if (t == 0)                                // d(l) from exponent bits
                d_local = inp_cur + 0.6931471805599453f *
                          (float)((int)(__float_as_uint(acc) >> 23) - 127);
            Msum += d_prev;                            // M(l) running total
            inp_cur = inp_next;
            buf ^= 1;
        }

        // ---- log_norm = M(ns) + ln(sum_t ea_t), fp32 reduction ----
        sh_red[t] = ea_f;
        __syncthreads();
        for (int o = 64; o > 0; o >>= 1) {
            if (t < o) sh_red[t] += sh_red[t + o];
            __syncthreads();
        }
        if (t == 0) out[b] = seqscore - (Msum + __logf(sh_red[0]));
        __syncthreads();                               // protect shared
    }
}

// ---------------------------------------------------------------------------
extern "C" void kernel_launch(void* const* d_in, const int* in_sizes, int n_in,
                              void* d_out, int out_size) {
    const float* inputs = (const float*)d_in[0];
    const int*   tags32 = (const int*)d_in[1];
    const int*   slen32 = (const int*)d_in[2];
    const float* trans  = (const float*)d_in[3];
    float* outp = (float*)d_out;

    crf_all<<<GRID, 128>>>(inputs, tags32, slen32, trans, outp);
}